// round 13
// baseline (speedup 1.0000x reference)
#include <cuda_runtime.h>

// pred/target: (2,2,128,128,128) fp32 contiguous. idx = bc*2^21 + d*2^14 + h*2^7 + w
#define NTOT 8388608
#define BC_STRIDE 2097152
#define D_STRIDE  16384

// After W+H passes: packed u32 per voxel = predEDT2 | targEDT2<<16.
// Real values <= 32258; sentinel = 0xC000 (49152): +rr (<=16129) stays < 65536.
__device__ unsigned int g_pt[NTOT];
__device__ double g_acc;
__device__ int g_count;

// ---------------------------------------------------------------------------
// Fused pass1 (W axis, two-sweep, byte-packed both tensors) +
// pass2 (H axis, pruned scan: one unconditional batch r=1..4 with 8
// independent LDS, single vote, rare sequential tail).
// One (bc,d) slab 128x128 per block; grid=512, block=256; 33KB smem.
// ---------------------------------------------------------------------------
__global__ void __launch_bounds__(256) k_pass12(const float* __restrict__ pred,
                                                const float* __restrict__ target) {
    __shared__ unsigned short md[128][130];   // byte-packed: pred | targ<<8
    const int tid = threadIdx.x;
    const long base = (long)blockIdx.x * 16384;

    if (blockIdx.x == 0 && tid == 0) g_acc = 0.0;

    // mask load, both tensors: byte = 0 (background) / 1 (foreground)
    const float4* p4 = (const float4*)(pred + base);
    const float4* t4 = (const float4*)(target + base);
    #pragma unroll
    for (int it = 0; it < 16; it++) {
        int idx = it * 256 + tid;            // 0..4095 float4
        float4 p = p4[idx], t = t4[idx];
        int r  = idx >> 5;
        int w4 = (idx & 31) * 4;
        unsigned u0 = (p.x >= 0.5f ? 1u : 0u) | (t.x >= 0.5f ? 0x100u : 0u);
        unsigned u1 = (p.y >= 0.5f ? 1u : 0u) | (t.y >= 0.5f ? 0x100u : 0u);
        unsigned u2 = (p.z >= 0.5f ? 1u : 0u) | (t.z >= 0.5f ? 0x100u : 0u);
        unsigned u3 = (p.w >= 0.5f ? 1u : 0u) | (t.w >= 0.5f ? 0x100u : 0u);
        *(unsigned*)&md[r][w4]     = u0 | (u1 << 16);
        *(unsigned*)&md[r][w4 + 2] = u2 | (u3 << 16);
    }
    __syncthreads();

    // pass1: forward/backward sweeps along w, thread = row. dist 255 = "no bg".
    if (tid < 128) {
        unsigned short* row = md[tid];
        int dp = 255, dt = 255;
        #pragma unroll 4
        for (int w = 0; w < 128; w++) {
            int m = row[w];
            dp = (m & 0xff)   ? min(dp + 1, 255) : 0;
            dt = (m & 0xff00) ? min(dt + 1, 255) : 0;
            row[w] = (unsigned short)(dp | (dt << 8));
        }
        int ep = 255, et = 255;
        #pragma unroll 4
        for (int w = 127; w >= 0; w--) {
            int v = row[w];
            int vp = v & 0xff, vt = v >> 8;
            ep = vp ? min(ep + 1, 255) : 0;
            et = vt ? min(et + 1, 255) : 0;
            row[w] = (unsigned short)(min(vp, ep) | (min(vt, et) << 8));
        }
    }
    __syncthreads();

    // pass2: out[x][w] = min_y (d(y)^2 + (x-y)^2).
    // warp = output row x, lanes = 32 consecutive w -> coalesced store.
    const int warp = tid >> 5, lane = tid & 31;
    for (int i = 0; i < 16; i++) {
        int x = warp + 8 * i;
        #pragma unroll
        for (int wg = 0; wg < 4; wg++) {
            int w = wg * 32 + lane;
            int v0 = md[x][w];
            int a0 = v0 & 0xff, c0 = v0 >> 8;
            int bp = a0 * a0;                // 255^2 = 65025 acts as +inf
            int bt = c0 * c0;

            // unconditional batch, radii 1..4: 8 independent LDS (clamped reads
            // are sound: g[0]+r^2 >= g[0]+x^2 = the true y=0 candidate)
            int l1 = md[max(x - 1, 0)][w],   h1 = md[min(x + 1, 127)][w];
            int l2 = md[max(x - 2, 0)][w],   h2 = md[min(x + 2, 127)][w];
            int l3 = md[max(x - 3, 0)][w],   h3 = md[min(x + 3, 127)][w];
            int l4 = md[max(x - 4, 0)][w],   h4 = md[min(x + 4, 127)][w];
            int a, c;
            a = l1 & 0xff; c = l1 >> 8; bp = min(bp, a * a + 1);  bt = min(bt, c * c + 1);
            a = h1 & 0xff; c = h1 >> 8; bp = min(bp, a * a + 1);  bt = min(bt, c * c + 1);
            a = l2 & 0xff; c = l2 >> 8; bp = min(bp, a * a + 4);  bt = min(bt, c * c + 4);
            a = h2 & 0xff; c = h2 >> 8; bp = min(bp, a * a + 4);  bt = min(bt, c * c + 4);
            a = l3 & 0xff; c = l3 >> 8; bp = min(bp, a * a + 9);  bt = min(bt, c * c + 9);
            a = h3 & 0xff; c = h3 >> 8; bp = min(bp, a * a + 9);  bt = min(bt, c * c + 9);
            a = l4 & 0xff; c = l4 >> 8; bp = min(bp, a * a + 16); bt = min(bt, c * c + 16);
            a = h4 & 0xff; c = h4 >> 8; bp = min(bp, a * a + 16); bt = min(bt, c * c + 16);

            // single vote; sequential tail is rare (P < 0.2%)
            if (!__all_sync(0xffffffffu, 25 >= max(bp, bt))) {
                for (int r = 5; r < 128; r++) {
                    if (__all_sync(0xffffffffu, r * r >= max(bp, bt))) break;
                    int rr = r * r;
                    int vl = md[max(x - r, 0)][w], vh = md[min(x + r, 127)][w];
                    int al = vl & 0xff, cl = vl >> 8;
                    int ah = vh & 0xff, ch = vh >> 8;
                    bp = min(bp, min(al * al + rr, ah * ah + rr));
                    bt = min(bt, min(cl * cl + rr, ch * ch + rr));
                }
            }
            bp = (bp > 32258) ? 49152 : bp;  // sentinel 0xC000: carry-safe
            bt = (bt > 32258) ? 49152 : bt;
            g_pt[base + x * 128 + w] = (unsigned)bp | ((unsigned)bt << 16);
        }
    }
}

// ---------------------------------------------------------------------------
// Pass3 (D axis, batched pruned scan on packed tile) + loss + final.
// Block = 512, tile = fixed (bc,h), w0..w0+63, all 128 d. grid=(2,128,4).
// ---------------------------------------------------------------------------
__global__ void __launch_bounds__(512) k_pass3(const float* __restrict__ pred,
                                               const float* __restrict__ target,
                                               const int* __restrict__ is_avg,
                                               float* __restrict__ out) {
    __shared__ unsigned int gpt[128][66];
    __shared__ double sd[16];

    const int tid = threadIdx.x;
    const int w0 = blockIdx.x * 64;
    const int h  = blockIdx.y;
    const int bc = blockIdx.z;
    const long base = (long)bc * BC_STRIDE + (long)h * 128 + w0;

    // stage packed tile: 128 rows x 32 uint2 = 4096 uint2
    #pragma unroll
    for (int it = 0; it < 8; it++) {
        int idx = it * 512 + tid;
        int d = idx >> 5, w2 = (idx & 31) * 2;
        long a = base + (long)d * D_STRIDE + w2;
        *(uint2*)&gpt[d][w2] = *(const uint2*)&g_pt[a];
    }
    __syncthreads();

    const int warp = tid >> 5, lane = tid & 31;
    double acc = 0.0;
    for (int i = 0; i < 8; i++) {
        int x = warp + 16 * i;
        #pragma unroll
        for (int wg = 0; wg < 2; wg++) {
            int w = wg * 32 + lane;
            unsigned v0 = gpt[x][w];
            int bp = (int)(v0 & 0xffffu);
            int bt = (int)(v0 >> 16);

            // unconditional batch, radii 1..4: 8 independent LDS
            unsigned l1 = gpt[max(x - 1, 0)][w],   h1 = gpt[min(x + 1, 127)][w];
            unsigned l2 = gpt[max(x - 2, 0)][w],   h2 = gpt[min(x + 2, 127)][w];
            unsigned l3 = gpt[max(x - 3, 0)][w],   h3 = gpt[min(x + 3, 127)][w];
            unsigned l4 = gpt[max(x - 4, 0)][w],   h4 = gpt[min(x + 4, 127)][w];
            bp = min(bp, min((int)(l1 & 0xffffu) + 1,  (int)(h1 & 0xffffu) + 1));
            bt = min(bt, min((int)(l1 >> 16)     + 1,  (int)(h1 >> 16)     + 1));
            bp = min(bp, min((int)(l2 & 0xffffu) + 4,  (int)(h2 & 0xffffu) + 4));
            bt = min(bt, min((int)(l2 >> 16)     + 4,  (int)(h2 >> 16)     + 4));
            bp = min(bp, min((int)(l3 & 0xffffu) + 9,  (int)(h3 & 0xffffu) + 9));
            bt = min(bt, min((int)(l3 >> 16)     + 9,  (int)(h3 >> 16)     + 9));
            bp = min(bp, min((int)(l4 & 0xffffu) + 16, (int)(h4 & 0xffffu) + 16));
            bt = min(bt, min((int)(l4 >> 16)     + 16, (int)(h4 >> 16)     + 16));

            if (!__all_sync(0xffffffffu, 25 >= max(bp, bt))) {
                for (int r = 5; r < 128; r++) {
                    if (__all_sync(0xffffffffu, r * r >= max(bp, bt))) break;
                    int rr = r * r;
                    unsigned vl = gpt[max(x - r, 0)][w], vh = gpt[min(x + r, 127)][w];
                    bp = min(bp, min((int)(vl & 0xffffu) + rr,
                                     (int)(vh & 0xffffu) + rr));
                    bt = min(bt, min((int)(vl >> 16) + rr,
                                     (int)(vh >> 16) + rr));
                }
            }
            long a = base + (long)x * D_STRIDE + w;
            float e = pred[a] - target[a];           // coalesced 128B
            acc += (double)(e * e * (float)(bp + bt));
        }
    }

    #pragma unroll
    for (int s = 16; s > 0; s >>= 1)
        acc += __shfl_down_sync(0xffffffffu, acc, s);
    if (lane == 0) sd[warp] = acc;
    __syncthreads();
    if (warp == 0) {
        double v = (lane < 16) ? sd[lane] : 0.0;
        #pragma unroll
        for (int s = 8; s > 0; s >>= 1)
            v += __shfl_down_sync(0xffffffffu, v, s);
        if (lane == 0) atomicAdd(&g_acc, v);
    }
    __syncthreads();

    // last block computes the final scalar
    if (tid == 0) {
        __threadfence();
        int old = atomicAdd(&g_count, 1);
        if (old == 2 * 128 * 4 - 1) {
            double m = g_acc / (double)NTOT;
            if (*is_avg == 0) m *= 2.0;      // * pred.shape[0]
            out[0] = (float)m;
            g_count = 0;                      // reset for next graph replay
        }
    }
}

extern "C" void kernel_launch(void* const* d_in, const int* in_sizes, int n_in,
                              void* d_out, int out_size) {
    const float* pred   = (const float*)d_in[0];
    const float* target = (const float*)d_in[1];
    const int*   is_avg = (const int*)d_in[2];
    float* out = (float*)d_out;

    k_pass12<<<512, 256>>>(pred, target);
    k_pass3<<<dim3(2, 128, 4), 512>>>(pred, target, is_avg, out);
}

// round 14
// speedup vs baseline: 1.1658x; 1.1658x over previous
#include <cuda_runtime.h>

// pred/target: (2,2,128,128,128) fp32 contiguous. idx = bc*2^21 + d*2^14 + h*2^7 + w
#define NTOT 8388608
#define BC_STRIDE 2097152
#define D_STRIDE  16384

// Squared EDT after W+H passes: integer <= 32258 -> u16. 65535 = inf sentinel.
__device__ unsigned short g_p16[NTOT];
__device__ unsigned short g_t16[NTOT];
__device__ double g_acc;
__device__ int g_count;

// ---------------------------------------------------------------------------
// Fused pass1 (W axis, split-row two-sweep with exact carry fix) +
// pass2 (H axis, pruned exact scan — round-8 loop verbatim).
// One (bc,d) slab 128x128 per block. grid=(512, 2 tensors), block=256.
// ---------------------------------------------------------------------------
__global__ void __launch_bounds__(256) k_pass12(const float* __restrict__ pred,
                                                const float* __restrict__ target) {
    __shared__ unsigned short dsq[128][130];   // mask -> dist -> dist^2
    __shared__ unsigned char carry_f[128];
    __shared__ unsigned char carry_b[128];
    const float* src = blockIdx.y ? target : pred;
    unsigned short* dst = blockIdx.y ? g_t16 : g_p16;
    const int tid = threadIdx.x;
    const long base = (long)blockIdx.x * 16384;

    if (blockIdx.x == 0 && blockIdx.y == 0 && tid == 0) g_acc = 0.0;

    // vectorized mask load: 0 = background, 255 = foreground
    const float4* src4 = (const float4*)(src + base);
    #pragma unroll
    for (int it = 0; it < 16; it++) {
        int idx = it * 256 + tid;            // 0..4095 float4
        float4 v = src4[idx];
        int r  = idx >> 5;
        int w4 = (idx & 31) * 4;
        *(ushort2*)&dsq[r][w4]     = make_ushort2(v.x >= 0.5f ? 255 : 0,
                                                  v.y >= 0.5f ? 255 : 0);
        *(ushort2*)&dsq[r][w4 + 2] = make_ushort2(v.z >= 0.5f ? 255 : 0,
                                                  v.w >= 0.5f ? 255 : 0);
    }
    __syncthreads();

    // pass1 on split rows: thread = (half, row); each owns 64 elements.
    const int row  = tid & 127;
    const int half = tid >> 7;
    const int w0   = half * 64;
    unsigned short* rp = dsq[row];

    // Phase A: local forward run-length (255 = "no background seen")
    {
        int d = 255;
        #pragma unroll 4
        for (int w = 0; w < 64; w++) {
            d = (rp[w0 + w] == 0) ? 0 : min(d + 1, 255);
            rp[w0 + w] = (unsigned short)d;
        }
        if (half == 0) carry_f[row] = (unsigned char)d;
    }
    __syncthreads();

    // Phase B: forward fix (right half) + local backward, store min(fwd,bwd)
    {
        int cf = carry_f[row];
        int b = 255;
        #pragma unroll 4
        for (int w = 63; w >= 0; w--) {
            int v = rp[w0 + w];
            if (half == 1) {
                int cand = (cf >= 255) ? 255 : min(cf + w + 1, 255);
                v = min(v, cand);               // exact dist through boundary
            }
            b = (v == 0) ? 0 : min(b + 1, 255);
            rp[w0 + w] = (unsigned short)min(v, b);
        }
        if (half == 1) carry_b[row] = (unsigned char)b;
    }
    __syncthreads();

    // Phase C: backward fix (left half) + square + sentinel
    {
        int cb = carry_b[row];
        #pragma unroll 4
        for (int w = 0; w < 64; w++) {
            int v = rp[w0 + w];
            if (half == 0) {
                int cand = (cb >= 255) ? 255 : min(cb + (64 - w), 255);
                v = min(v, cand);               // exact dist through boundary
            }
            rp[w0 + w] = (v == 255) ? (unsigned short)65535
                                    : (unsigned short)(v * v);
        }
    }
    __syncthreads();

    // pass2 (round-8 loop): out[x][w] = min_y (dsq[y][w] + (x-y)^2), pruned.
    // warp = output row x, lanes = 32 consecutive w -> coalesced global store.
    const int warp = tid >> 5, lane = tid & 31;
    for (int i = 0; i < 16; i++) {
        int x = warp + 8 * i;
        #pragma unroll
        for (int wg = 0; wg < 4; wg++) {
            int w = wg * 32 + lane;
            int b = dsq[x][w];
            int rr = 1;
            for (int r = 1; r < 128; r++) {
                if (__all_sync(0xffffffffu, rr >= b)) break;
                int lo = x - r, hi = x + r;
                if (lo >= 0)  b = min(b, (int)dsq[lo][w] + rr);
                if (hi < 128) b = min(b, (int)dsq[hi][w] + rr);
                rr += 2 * r + 1;
            }
            dst[base + x * 128 + w] =
                (b > 32258) ? (unsigned short)65535 : (unsigned short)b;
        }
    }
}

// ---------------------------------------------------------------------------
// Pass3 (D axis, pruned scan, both tensors — round-8 loop verbatim) fused
// with the loss reduction and the final scalar (last-block pattern).
// Block = 512, tile = fixed (bc,h), w0..w0+63, all 128 d. grid=(2,128,4).
// ---------------------------------------------------------------------------
__global__ void __launch_bounds__(512) k_pass3(const float* __restrict__ pred,
                                               const float* __restrict__ target,
                                               const int* __restrict__ is_avg,
                                               float* __restrict__ out) {
    __shared__ unsigned short gp[128][66];
    __shared__ unsigned short gt[128][66];
    __shared__ double sd[16];

    const int tid = threadIdx.x;
    const int w0 = blockIdx.x * 64;
    const int h  = blockIdx.y;
    const int bc = blockIdx.z;
    const long base = (long)bc * BC_STRIDE + (long)h * 128 + w0;

    // stage g tiles (coalesced ushort2 loads)
    #pragma unroll
    for (int it = 0; it < 8; it++) {
        int idx = it * 512 + tid;            // 0..4095 ushort2
        int d = idx >> 5, w2 = (idx & 31) * 2;
        long a = base + (long)d * D_STRIDE + w2;
        *(ushort2*)&gp[d][w2] = *(const ushort2*)&g_p16[a];
        *(ushort2*)&gt[d][w2] = *(const ushort2*)&g_t16[a];
    }
    __syncthreads();

    // pruned scans along d + inline loss (round-8 loop)
    const int warp = tid >> 5, lane = tid & 31;
    double acc = 0.0;
    for (int i = 0; i < 8; i++) {
        int x = warp + 16 * i;
        #pragma unroll
        for (int wg = 0; wg < 2; wg++) {
            int w = wg * 32 + lane;
            int bp = gp[x][w];
            int bt = gt[x][w];
            int rr = 1;
            for (int r = 1; r < 128; r++) {
                if (__all_sync(0xffffffffu, rr >= max(bp, bt))) break;
                int lo = x - r, hi = x + r;
                if (lo >= 0) {
                    bp = min(bp, (int)gp[lo][w] + rr);
                    bt = min(bt, (int)gt[lo][w] + rr);
                }
                if (hi < 128) {
                    bp = min(bp, (int)gp[hi][w] + rr);
                    bt = min(bt, (int)gt[hi][w] + rr);
                }
                rr += 2 * r + 1;
            }
            long a = base + (long)x * D_STRIDE + w;
            float e = pred[a] - target[a];               // coalesced 128B
            acc += (double)(e * e * (float)(bp + bt));   // <= 96774: exact f32
        }
    }

    // warp-shuffle reduce, then cross-warp
    #pragma unroll
    for (int s = 16; s > 0; s >>= 1)
        acc += __shfl_down_sync(0xffffffffu, acc, s);
    if (lane == 0) sd[warp] = acc;
    __syncthreads();
    if (warp == 0) {
        double v = (lane < 16) ? sd[lane] : 0.0;
        #pragma unroll
        for (int s = 8; s > 0; s >>= 1)
            v += __shfl_down_sync(0xffffffffu, v, s);
        if (lane == 0) atomicAdd(&g_acc, v);
    }
    __syncthreads();

    // last block computes the final scalar (folds old k_final)
    if (tid == 0) {
        __threadfence();
        int old = atomicAdd(&g_count, 1);
        if (old == 2 * 128 * 4 - 1) {
            double m = g_acc / (double)NTOT;
            if (*is_avg == 0) m *= 2.0;      // * pred.shape[0]
            out[0] = (float)m;
            g_count = 0;                      // reset for next graph replay
        }
    }
}

extern "C" void kernel_launch(void* const* d_in, const int* in_sizes, int n_in,
                              void* d_out, int out_size) {
    const float* pred   = (const float*)d_in[0];
    const float* target = (const float*)d_in[1];
    const int*   is_avg = (const int*)d_in[2];
    float* out = (float*)d_out;

    k_pass12<<<dim3(512, 2), 256>>>(pred, target);
    k_pass3<<<dim3(2, 128, 4), 512>>>(pred, target, is_avg, out);
}

// round 15
// speedup vs baseline: 1.2811x; 1.0988x over previous
#include <cuda_runtime.h>

// pred/target: (2,2,128,128,128) fp32 contiguous. idx = bc*2^21 + d*2^14 + h*2^7 + w
#define NTOT 8388608
#define BC_STRIDE 2097152
#define D_STRIDE  16384

// Squared EDT after W+H passes: integer <= 32258 -> u16. 65535 = inf sentinel.
__device__ unsigned short g_p16[NTOT];
__device__ unsigned short g_t16[NTOT];
__device__ double g_acc;
__device__ int g_count;

// ---------------------------------------------------------------------------
// Fused pass1 (W axis, two-sweep + square) + pass2 (H axis, pruned exact scan)
// One (bc,d) slab 128x128 per block. grid=(512, 2 tensors), block=256.
// (Round-8 kernel, verbatim.)
// ---------------------------------------------------------------------------
__global__ void __launch_bounds__(256) k_pass12(const float* __restrict__ pred,
                                                const float* __restrict__ target) {
    __shared__ unsigned short dsq[128][130];
    const float* src = blockIdx.y ? target : pred;
    unsigned short* dst = blockIdx.y ? g_t16 : g_p16;
    const int tid = threadIdx.x;
    const long base = (long)blockIdx.x * 16384;

    if (blockIdx.x == 0 && blockIdx.y == 0 && tid == 0) g_acc = 0.0;

    // vectorized mask load: 0 = background, 255 = foreground
    const float4* src4 = (const float4*)(src + base);
    #pragma unroll
    for (int it = 0; it < 16; it++) {
        int idx = it * 256 + tid;            // 0..4095 float4
        float4 v = src4[idx];
        int r  = idx >> 5;                   // 32 float4 per row
        int w4 = (idx & 31) * 4;
        *(ushort2*)&dsq[r][w4]     = make_ushort2(v.x >= 0.5f ? 255 : 0,
                                                  v.y >= 0.5f ? 255 : 0);
        *(ushort2*)&dsq[r][w4 + 2] = make_ushort2(v.z >= 0.5f ? 255 : 0,
                                                  v.w >= 0.5f ? 255 : 0);
    }
    __syncthreads();

    // pass1: forward/backward sweep along w (thread = row h); square folded in.
    if (tid < 128) {
        unsigned short* row = dsq[tid];
        int d = 255;
        #pragma unroll 4
        for (int w = 0; w < 128; w++) {
            d = (row[w] == 0) ? 0 : min(d + 1, 255);
            row[w] = (unsigned short)d;
        }
        int db = 255;
        #pragma unroll 4
        for (int w = 127; w >= 0; w--) {
            int df = row[w];
            db = (df == 0) ? 0 : min(db + 1, 255);
            int m = min(df, db);
            row[w] = (m == 255) ? (unsigned short)65535 : (unsigned short)(m * m);
        }
    }
    __syncthreads();

    // pass2: out[x][w] = min_y (dsq[y][w] + (x-y)^2), pruned outward scan.
    // warp = output row x, lanes = 32 consecutive w -> coalesced global store.
    const int warp = tid >> 5, lane = tid & 31;
    for (int i = 0; i < 16; i++) {
        int x = warp + 8 * i;
        #pragma unroll
        for (int wg = 0; wg < 4; wg++) {
            int w = wg * 32 + lane;
            int b = dsq[x][w];
            int rr = 1;
            for (int r = 1; r < 128; r++) {
                if (__all_sync(0xffffffffu, rr >= b)) break;
                int lo = x - r, hi = x + r;
                if (lo >= 0)  b = min(b, (int)dsq[lo][w] + rr);
                if (hi < 128) b = min(b, (int)dsq[hi][w] + rr);
                rr += 2 * r + 1;
            }
            dst[base + x * 128 + w] =
                (b > 32258) ? (unsigned short)65535 : (unsigned short)b;
        }
    }
}

// ---------------------------------------------------------------------------
// Pass3 (D axis, pruned scan, both tensors) fused with the loss reduction
// (round-8 kernel) + the final scalar via last-block pattern (only delta).
// Block = 512, tile = fixed (bc,h), w0..w0+63, all 128 d. grid=(2,128,4).
// ---------------------------------------------------------------------------
__global__ void __launch_bounds__(512) k_pass3(const float* __restrict__ pred,
                                               const float* __restrict__ target,
                                               const int* __restrict__ is_avg,
                                               float* __restrict__ out) {
    __shared__ unsigned short gp[128][66];
    __shared__ unsigned short gt[128][66];
    __shared__ double sd[16];

    const int tid = threadIdx.x;
    const int w0 = blockIdx.x * 64;
    const int h  = blockIdx.y;
    const int bc = blockIdx.z;
    const long base = (long)bc * BC_STRIDE + (long)h * 128 + w0;

    // stage g tiles (coalesced ushort2 loads: 64 u16 = 128B per row)
    #pragma unroll
    for (int it = 0; it < 8; it++) {
        int idx = it * 512 + tid;            // 0..4095 ushort2
        int d = idx >> 5, w2 = (idx & 31) * 2;
        long a = base + (long)d * D_STRIDE + w2;
        *(ushort2*)&gp[d][w2] = *(const ushort2*)&g_p16[a];
        *(ushort2*)&gt[d][w2] = *(const ushort2*)&g_t16[a];
    }
    __syncthreads();

    // pruned scans along d + inline loss
    const int warp = tid >> 5, lane = tid & 31;
    double acc = 0.0;
    for (int i = 0; i < 8; i++) {
        int x = warp + 16 * i;
        #pragma unroll
        for (int wg = 0; wg < 2; wg++) {
            int w = wg * 32 + lane;
            int bp = gp[x][w];
            int bt = gt[x][w];
            int rr = 1;
            for (int r = 1; r < 128; r++) {
                if (__all_sync(0xffffffffu, rr >= max(bp, bt))) break;
                int lo = x - r, hi = x + r;
                if (lo >= 0) {
                    bp = min(bp, (int)gp[lo][w] + rr);
                    bt = min(bt, (int)gt[lo][w] + rr);
                }
                if (hi < 128) {
                    bp = min(bp, (int)gp[hi][w] + rr);
                    bt = min(bt, (int)gt[hi][w] + rr);
                }
                rr += 2 * r + 1;
            }
            long a = base + (long)x * D_STRIDE + w;
            float e = pred[a] - target[a];               // coalesced 128B
            acc += (double)(e * e * (float)(bp + bt));   // <= 96774: exact f32
        }
    }

    // warp-shuffle reduce, then cross-warp
    #pragma unroll
    for (int s = 16; s > 0; s >>= 1)
        acc += __shfl_down_sync(0xffffffffu, acc, s);
    if (lane == 0) sd[warp] = acc;
    __syncthreads();
    if (warp == 0) {
        double v = (lane < 16) ? sd[lane] : 0.0;
        #pragma unroll
        for (int s = 8; s > 0; s >>= 1)
            v += __shfl_down_sync(0xffffffffu, v, s);
        if (lane == 0) atomicAdd(&g_acc, v);
    }
    __syncthreads();

    // last block computes the final scalar (replaces the old k_final launch)
    if (tid == 0) {
        __threadfence();
        int old = atomicAdd(&g_count, 1);
        if (old == 2 * 128 * 4 - 1) {
            double m = g_acc / (double)NTOT;
            if (*is_avg == 0) m *= 2.0;      // * pred.shape[0]
            out[0] = (float)m;
            g_count = 0;                      // reset for next graph replay
        }
    }
}

extern "C" void kernel_launch(void* const* d_in, const int* in_sizes, int n_in,
                              void* d_out, int out_size) {
    const float* pred   = (const float*)d_in[0];
    const float* target = (const float*)d_in[1];
    const int*   is_avg = (const int*)d_in[2];
    float* out = (float*)d_out;

    k_pass12<<<dim3(512, 2), 256>>>(pred, target);
    k_pass3<<<dim3(2, 128, 4), 512>>>(pred, target, is_avg, out);
}